// round 8
// baseline (speedup 1.0000x reference)
#include <cuda_runtime.h>

#define NN 100000
#define F_IN 256
#define CH 16
#define CH2 8
#define NL 7

// ---------------- scratch (static device memory; no allocs) ----------------
__device__ __align__(128) float g_hs  [NN * CH];   // layer1 pre-scaled transform
__device__ __align__(128) float g_out1[NN * CH];   // layer1 accumulator
__device__ __align__(128) float g_hs2 [NN * CH2];  // layer2 pre-scaled transform (padded)
__device__ __align__(128) float g_out2[NN * CH2];  // layer2 accumulator (padded)
__device__ float g_dinv[NN];
__device__ int   g_deg [NN];

// vector float4 reduction (no return): red.global.add.v4.f32
__device__ __forceinline__ void red_add_f32x4(float* p, float a, float b, float c, float d) {
    asm volatile("red.global.add.v4.f32 [%0], {%1, %2, %3, %4};"
                 :: "l"(p), "f"(a), "f"(b), "f"(c), "f"(d) : "memory");
}

// packed dual fp32 FMA (sm_100a+): d.lo += a.lo*b.lo ; d.hi += a.hi*b.hi
__device__ __forceinline__ void ffma2(unsigned long long& d,
                                      unsigned long long a,
                                      unsigned long long b) {
    asm("fma.rn.f32x2 %0, %1, %2, %0;" : "+l"(d) : "l"(a), "l"(b));
}
__device__ __forceinline__ float f32x2_sum(unsigned long long v) {
    float lo = __uint_as_float((unsigned int)(v & 0xffffffffull));
    float hi = __uint_as_float((unsigned int)(v >> 32));
    return lo + hi;
}
__device__ __forceinline__ unsigned long long pack2(float a, float b) {
    return (unsigned long long)__float_as_uint(a)
         | ((unsigned long long)__float_as_uint(b) << 32);
}

// ---------------- degree / norm ----------------
__global__ void k_init_deg() {
    int i = blockIdx.x * blockDim.x + threadIdx.x;
    if (i < NN) g_deg[i] = 1;   // self loop
}

__global__ void k_deg(const int* __restrict__ dst, int E) {
    int i = blockIdx.x * blockDim.x + threadIdx.x;
    if (i < E) atomicAdd(&g_deg[dst[i]], 1);
}

__global__ void k_dinv() {
    int i = blockIdx.x * blockDim.x + threadIdx.x;
    if (i < NN) g_dinv[i] = rsqrtf((float)g_deg[i]);
}

// ---------------- GEMM1 v4: direct-LDG, high occupancy ----------------
// Thread g: row = g>>2, colset cs = g&3 (4 output cols each).
// The 4 lanes of a row issue IDENTICAL x addresses -> L1 dedup, no extra HBM
// traffic; consecutive k-iters reuse the 128B line from L1 (7/8 hit rate).
// W0 in smem, packed per k-pair as u64: Wp[p*32 + cs*8 + j*2 + (k&1)].
// Per float4 iter (4 k): 1 LDG.128 + 4 LDS.128 (4-way broadcast) + 8 FFMA2.
// No syncthreads in the loop, ~44 regs -> near-full occupancy, MLP from unroll.
__global__ void __launch_bounds__(256) k_gemm1(const float* __restrict__ x,
                                               const float* __restrict__ W0) {
    __shared__ float Wp[128 * 32];   // 16 KB
    const int tid = threadIdx.x;

    // stage W0 packed: Wp[(k>>1)*32 + (col>>2)*8 + (col&3)*2 + (k&1)] = W0[k*16+col]
    #pragma unroll
    for (int i = 0; i < 16; i++) {
        int idx = tid + 256 * i;
        int k   = idx >> 4;
        int col = idx & 15;
        Wp[(k >> 1) * 32 + (col >> 2) * 8 + (col & 3) * 2 + (k & 1)] = W0[idx];
    }
    __syncthreads();

    int g   = blockIdx.x * 256 + tid;
    int row = g >> 2;
    int cs  = g & 3;
    if (row >= NN) return;

    const float4* xr = (const float4*)(x + (size_t)row * F_IN);

    unsigned long long a0 = 0ull, a1 = 0ull, a2 = 0ull, a3 = 0ull;

    #pragma unroll 8
    for (int i = 0; i < 64; i++) {
        float4 v = __ldg(xr + i);
        unsigned long long xlo = pack2(v.x, v.y);   // k-pair 2i
        unsigned long long xhi = pack2(v.z, v.w);   // k-pair 2i+1
        const float* wp0 = Wp + (2 * i) * 32 + cs * 8;
        ulonglong2 wA = *(const ulonglong2*)wp0;        // pair 2i,   cols j0,j1
        ulonglong2 wB = *(const ulonglong2*)(wp0 + 4);  // pair 2i,   cols j2,j3
        ulonglong2 wC = *(const ulonglong2*)(wp0 + 32); // pair 2i+1, cols j0,j1
        ulonglong2 wD = *(const ulonglong2*)(wp0 + 36); // pair 2i+1, cols j2,j3
        ffma2(a0, xlo, wA.x);
        ffma2(a1, xlo, wA.y);
        ffma2(a2, xlo, wB.x);
        ffma2(a3, xlo, wB.y);
        ffma2(a0, xhi, wC.x);
        ffma2(a1, xhi, wC.y);
        ffma2(a2, xhi, wD.x);
        ffma2(a3, xhi, wD.y);
    }

    float di = g_dinv[row];
    float4 o = make_float4(f32x2_sum(a0) * di, f32x2_sum(a1) * di,
                           f32x2_sum(a2) * di, f32x2_sum(a3) * di);
    *(float4*)(g_hs   + (size_t)row * CH + 4 * cs) = o;
    *(float4*)(g_out1 + (size_t)row * CH + 4 * cs) = o;   // self-loop init
}

// ---------------- edge scatter, layer 1 (16 floats/row, 4 threads/edge) ----------------
__global__ void k_edge1(const int* __restrict__ src, const int* __restrict__ dst, int E) {
    int t = blockIdx.x * blockDim.x + threadIdx.x;
    if (t >= 4 * E) return;
    int e = t >> 2;
    int c = t & 3;
    int s = src[e];
    int d = dst[e];
    float4 v = ((const float4*)(g_hs + (size_t)s * CH))[c];
    red_add_f32x4((float*)(((float4*)(g_out1 + (size_t)d * CH)) + c), v.x, v.y, v.z, v.w);
}

// ---------------- mid: h1 = relu(out1*dinv); hs2 = (h1 @ W1)*dinv; init out2 ----------
__global__ void __launch_bounds__(256) k_mid(const float* __restrict__ W1) {
    __shared__ float W1s[CH * NL];
    if (threadIdx.x < CH * NL) W1s[threadIdx.x] = W1[threadIdx.x];
    __syncthreads();

    int t = blockIdx.x * blockDim.x + threadIdx.x;
    int row0 = t * 4;
    if (row0 >= NN) return;   // NN divisible by 4

    float h[4][CH];
    float di[4];
    #pragma unroll
    for (int r = 0; r < 4; r++) {
        int row = row0 + r;
        di[r] = g_dinv[row];
        #pragma unroll
        for (int q = 0; q < 4; q++) {
            float4 v = *(const float4*)(g_out1 + (size_t)row * CH + q * 4);
            h[r][q * 4 + 0] = fmaxf(v.x * di[r], 0.f);
            h[r][q * 4 + 1] = fmaxf(v.y * di[r], 0.f);
            h[r][q * 4 + 2] = fmaxf(v.z * di[r], 0.f);
            h[r][q * 4 + 3] = fmaxf(v.w * di[r], 0.f);
        }
    }

    float acc[4][NL];
    #pragma unroll
    for (int r = 0; r < 4; r++)
        #pragma unroll
        for (int c = 0; c < NL; c++) acc[r][c] = 0.f;

    #pragma unroll
    for (int jj = 0; jj < CH; jj++) {
        #pragma unroll
        for (int c = 0; c < NL; c++) {
            float w = W1s[jj * NL + c];
            #pragma unroll
            for (int r = 0; r < 4; r++) acc[r][c] += h[r][jj] * w;
        }
    }

    #pragma unroll
    for (int r = 0; r < 4; r++) {
        int row = row0 + r;
        float4 lo = make_float4(acc[r][0] * di[r], acc[r][1] * di[r],
                                acc[r][2] * di[r], acc[r][3] * di[r]);
        float4 hi = make_float4(acc[r][4] * di[r], acc[r][5] * di[r],
                                acc[r][6] * di[r], 0.f);
        *(float4*)(g_hs2  + (size_t)row * CH2)     = lo;
        *(float4*)(g_hs2  + (size_t)row * CH2 + 4) = hi;
        *(float4*)(g_out2 + (size_t)row * CH2)     = lo;   // self loop
        *(float4*)(g_out2 + (size_t)row * CH2 + 4) = hi;
    }
}

// ---------------- edge scatter, layer 2 (8 floats/row padded, 2 threads/edge) ----------
__global__ void k_edge2(const int* __restrict__ src, const int* __restrict__ dst, int E) {
    int t = blockIdx.x * blockDim.x + threadIdx.x;
    if (t >= 2 * E) return;
    int e = t >> 1;
    int c = t & 1;
    int s = src[e];
    int d = dst[e];
    float4 v = ((const float4*)(g_hs2 + (size_t)s * CH2))[c];
    red_add_f32x4((float*)(((float4*)(g_out2 + (size_t)d * CH2)) + c), v.x, v.y, v.z, v.w);
}

// ---------------- finalize: out = exp(out2*dinv) + 1 ----------------
__global__ void k_final(float* __restrict__ out) {
    int t = blockIdx.x * blockDim.x + threadIdx.x;
    if (t >= NN * NL) return;
    int i = t / NL;
    int j = t - i * NL;
    out[t] = expf(g_out2[(size_t)i * CH2 + j] * g_dinv[i]) + 1.0f;
}

// ---------------- launch ----------------
extern "C" void kernel_launch(void* const* d_in, const int* in_sizes, int n_in,
                              void* d_out, int out_size) {
    const float* x  = (const float*)d_in[0];
    const float* W0 = (const float*)d_in[1];
    const float* W1 = (const float*)d_in[2];
    const int*   ei = (const int*)d_in[3];
    const int E = in_sizes[3] / 2;
    const int* src = ei;
    const int* dst = ei + E;
    float* out = (float*)d_out;

    k_init_deg<<<(NN + 255) / 256, 256>>>();
    k_deg<<<(E + 255) / 256, 256>>>(dst, E);
    k_dinv<<<(NN + 255) / 256, 256>>>();

    k_gemm1<<<(4 * NN + 255) / 256, 256>>>(x, W0);

    k_edge1<<<(4 * E + 255) / 256, 256>>>(src, dst, E);

    k_mid<<<(NN / 4 + 255) / 256, 256>>>(W1);

    k_edge2<<<(2 * E + 255) / 256, 256>>>(src, dst, E);

    k_final<<<(NN * NL + 255) / 256, 256>>>(out);
}

// round 9
// speedup vs baseline: 1.2598x; 1.2598x over previous
#include <cuda_runtime.h>

#define NN 100000
#define F_IN 256
#define CH 16
#define CH2 8
#define NL 7

// ---------------- scratch (static device memory; no allocs) ----------------
__device__ __align__(128) float g_hs  [NN * CH];   // layer1 pre-scaled transform
__device__ __align__(128) float g_out1[NN * CH];   // layer1 accumulator
__device__ __align__(128) float g_hs2 [NN * CH2];  // layer2 pre-scaled transform (padded)
__device__ __align__(128) float g_out2[NN * CH2];  // layer2 accumulator (padded)
__device__ float g_dinv[NN];
__device__ int   g_deg [NN];

// vector float4 reduction (no return): red.global.add.v4.f32
__device__ __forceinline__ void red_add_f32x4(float* p, float a, float b, float c, float d) {
    asm volatile("red.global.add.v4.f32 [%0], {%1, %2, %3, %4};"
                 :: "l"(p), "f"(a), "f"(b), "f"(c), "f"(d) : "memory");
}

// packed dual fp32 FMA (sm_100a+): d.lo += a.lo*b.lo ; d.hi += a.hi*b.hi
__device__ __forceinline__ void ffma2(unsigned long long& d,
                                      unsigned long long a,
                                      unsigned long long b) {
    asm("fma.rn.f32x2 %0, %1, %2, %0;" : "+l"(d) : "l"(a), "l"(b));
}
__device__ __forceinline__ float f32x2_sum(unsigned long long v) {
    float lo = __uint_as_float((unsigned int)(v & 0xffffffffull));
    float hi = __uint_as_float((unsigned int)(v >> 32));
    return lo + hi;
}

// ---------------- degree / norm ----------------
__global__ void k_deg(const int* __restrict__ dst, int E) {
    int i = blockIdx.x * blockDim.x + threadIdx.x;
    if (i < E) atomicAdd(&g_deg[dst[i]], 1);
}

__global__ void k_dinv() {
    int i = blockIdx.x * blockDim.x + threadIdx.x;
    if (i < NN) g_dinv[i] = rsqrtf((float)(g_deg[i] + 1));   // +1 self loop
}

// ---------------- GEMM1 v5: smem-tiled FFMA2 + cp.async double buffer ----------------
// 128 threads, TR=96 rows/block, k-chunk 32, 2-stage cp.async pipeline.
// Thread (rg=tid>>2 in 0..31, cg=tid&3) -> rows {rg+32c, c=0..2}, cols {4cg..4cg+3}.
// xs rows padded to 36 floats (bank-stride 4 -> 8 rows hit distinct banks).
// Wp packs k-pairs: pair p, col j at Wp[p*32 + 2j + (k&1)] -> thread's 4 cols
// = 2 LDS.128 at 4 distinct addresses (8-way broadcast).
// Per k-pair/thread: 3 LDS.64(x) + 2 LDS.128(w) + 12 FFMA2.
#define TR 96
#define KCH 32
#define NCHUNK (F_IN / KCH)

__device__ __forceinline__ void stage_chunk(const float* __restrict__ x,
                                            int row0, int kc, float* xsbuf, int tid) {
    #pragma unroll
    for (int it = 0; it < 6; it++) {
        int f = tid + 128 * it;
        int r = f >> 3;
        int q = f & 7;
        int grow = row0 + r;
        int ok = (grow < NN);
        const float* gp = x + (size_t)(ok ? grow : 0) * F_IN + kc + 4 * q;
        unsigned saddr = (unsigned)__cvta_generic_to_shared(xsbuf + r * 36 + 4 * q);
        int sz = ok ? 16 : 0;
        asm volatile("cp.async.cg.shared.global [%0], [%1], 16, %2;"
                     :: "r"(saddr), "l"(gp), "r"(sz));
    }
}

__global__ void __launch_bounds__(128) k_gemm1(const float* __restrict__ x,
                                               const float* __restrict__ W0) {
    __shared__ float xs[2][TR * 36];   // 2 x 13824 B
    __shared__ float Wp[128 * 32];     // 16384 B  (128 k-pairs x 16 cols x 2)
    const int tid = threadIdx.x;
    const int rg  = tid >> 2;
    const int cg  = tid & 3;
    const int row0 = blockIdx.x * TR;

    // stage W0 packed: Wp[(k>>1)*32 + 2*col + (k&1)] = W0[k*16+col]
    #pragma unroll
    for (int i = 0; i < 32; i++) {
        int idx = tid + 128 * i;
        int k   = idx >> 4;
        int col = idx & 15;
        Wp[(k >> 1) * 32 + 2 * col + (k & 1)] = W0[idx];
    }

    // prologue: stage chunk 0
    stage_chunk(x, row0, 0, xs[0], tid);
    asm volatile("cp.async.commit_group;");

    unsigned long long acc[3][4];
    #pragma unroll
    for (int c = 0; c < 3; c++)
        #pragma unroll
        for (int j = 0; j < 4; j++) acc[c][j] = 0ull;

    for (int ch = 0; ch < NCHUNK; ch++) {
        if (ch + 1 < NCHUNK) {
            stage_chunk(x, row0, (ch + 1) * KCH, xs[(ch + 1) & 1], tid);
            asm volatile("cp.async.commit_group;");
            asm volatile("cp.async.wait_group 1;");
        } else {
            asm volatile("cp.async.wait_group 0;");
        }
        __syncthreads();   // chunk ch data visible to all; also fences W on ch==0

        const float* buf = xs[ch & 1];
        const int pbase = ch * (KCH / 2);
        #pragma unroll
        for (int kp = 0; kp < KCH / 2; kp++) {
            const float* wp0 = Wp + (pbase + kp) * 32 + 8 * cg;
            ulonglong2 wA = *(const ulonglong2*)wp0;        // cols 4cg, 4cg+1
            ulonglong2 wB = *(const ulonglong2*)(wp0 + 4);  // cols 4cg+2, 4cg+3
            #pragma unroll
            for (int c = 0; c < 3; c++) {
                unsigned long long xv =
                    *(const unsigned long long*)(buf + (rg + 32 * c) * 36 + 2 * kp);
                ffma2(acc[c][0], xv, wA.x);
                ffma2(acc[c][1], xv, wA.y);
                ffma2(acc[c][2], xv, wB.x);
                ffma2(acc[c][3], xv, wB.y);
            }
        }
        __syncthreads();   // compute done before next stage overwrites this buffer
    }

    #pragma unroll
    for (int c = 0; c < 3; c++) {
        int grow = row0 + rg + 32 * c;
        if (grow < NN) {
            float di = g_dinv[grow];
            float4 o = make_float4(f32x2_sum(acc[c][0]) * di,
                                   f32x2_sum(acc[c][1]) * di,
                                   f32x2_sum(acc[c][2]) * di,
                                   f32x2_sum(acc[c][3]) * di);
            *(float4*)(g_hs   + (size_t)grow * CH + 4 * cg) = o;
            *(float4*)(g_out1 + (size_t)grow * CH + 4 * cg) = o;   // self-loop init
        }
    }
}

// ---------------- edge scatter, layer 1 (16 floats/row, 4 threads/edge) ----------------
__global__ void k_edge1(const int* __restrict__ src, const int* __restrict__ dst, int E) {
    int t = blockIdx.x * blockDim.x + threadIdx.x;
    if (t >= 4 * E) return;
    int e = t >> 2;
    int c = t & 3;
    int s = src[e];
    int d = dst[e];
    float4 v = ((const float4*)(g_hs + (size_t)s * CH))[c];
    red_add_f32x4((float*)(((float4*)(g_out1 + (size_t)d * CH)) + c), v.x, v.y, v.z, v.w);
}

// ---------------- mid: h1 = relu(out1*dinv); hs2 = (h1 @ W1)*dinv; init out2 ----------
__global__ void __launch_bounds__(256) k_mid(const float* __restrict__ W1) {
    __shared__ float W1s[CH * NL];
    if (threadIdx.x < CH * NL) W1s[threadIdx.x] = W1[threadIdx.x];
    __syncthreads();

    int t = blockIdx.x * blockDim.x + threadIdx.x;
    int row0 = t * 4;
    if (row0 >= NN) return;   // NN divisible by 4

    float h[4][CH];
    float di[4];
    #pragma unroll
    for (int r = 0; r < 4; r++) {
        int row = row0 + r;
        di[r] = g_dinv[row];
        #pragma unroll
        for (int q = 0; q < 4; q++) {
            float4 v = *(const float4*)(g_out1 + (size_t)row * CH + q * 4);
            h[r][q * 4 + 0] = fmaxf(v.x * di[r], 0.f);
            h[r][q * 4 + 1] = fmaxf(v.y * di[r], 0.f);
            h[r][q * 4 + 2] = fmaxf(v.z * di[r], 0.f);
            h[r][q * 4 + 3] = fmaxf(v.w * di[r], 0.f);
        }
    }

    float acc[4][NL];
    #pragma unroll
    for (int r = 0; r < 4; r++)
        #pragma unroll
        for (int c = 0; c < NL; c++) acc[r][c] = 0.f;

    #pragma unroll
    for (int jj = 0; jj < CH; jj++) {
        #pragma unroll
        for (int c = 0; c < NL; c++) {
            float w = W1s[jj * NL + c];
            #pragma unroll
            for (int r = 0; r < 4; r++) acc[r][c] += h[r][jj] * w;
        }
    }

    #pragma unroll
    for (int r = 0; r < 4; r++) {
        int row = row0 + r;
        float4 lo = make_float4(acc[r][0] * di[r], acc[r][1] * di[r],
                                acc[r][2] * di[r], acc[r][3] * di[r]);
        float4 hi = make_float4(acc[r][4] * di[r], acc[r][5] * di[r],
                                acc[r][6] * di[r], 0.f);
        *(float4*)(g_hs2  + (size_t)row * CH2)     = lo;
        *(float4*)(g_hs2  + (size_t)row * CH2 + 4) = hi;
        *(float4*)(g_out2 + (size_t)row * CH2)     = lo;   // self loop
        *(float4*)(g_out2 + (size_t)row * CH2 + 4) = hi;
    }
}

// ---------------- edge scatter, layer 2 (8 floats/row padded, 2 threads/edge) ----------
__global__ void k_edge2(const int* __restrict__ src, const int* __restrict__ dst, int E) {
    int t = blockIdx.x * blockDim.x + threadIdx.x;
    if (t >= 2 * E) return;
    int e = t >> 1;
    int c = t & 1;
    int s = src[e];
    int d = dst[e];
    float4 v = ((const float4*)(g_hs2 + (size_t)s * CH2))[c];
    red_add_f32x4((float*)(((float4*)(g_out2 + (size_t)d * CH2)) + c), v.x, v.y, v.z, v.w);
}

// ---------------- finalize: out = exp(out2*dinv) + 1 ----------------
__global__ void k_final(float* __restrict__ out) {
    int t = blockIdx.x * blockDim.x + threadIdx.x;
    if (t >= NN * NL) return;
    int i = t / NL;
    int j = t - i * NL;
    out[t] = expf(g_out2[(size_t)i * CH2 + j] * g_dinv[i]) + 1.0f;
}

// ---------------- launch ----------------
extern "C" void kernel_launch(void* const* d_in, const int* in_sizes, int n_in,
                              void* d_out, int out_size) {
    const float* x  = (const float*)d_in[0];
    const float* W0 = (const float*)d_in[1];
    const float* W1 = (const float*)d_in[2];
    const int*   ei = (const int*)d_in[3];
    const int E = in_sizes[3] / 2;
    const int* src = ei;
    const int* dst = ei + E;
    float* out = (float*)d_out;

    static void* deg_ptr = nullptr;
    if (!deg_ptr) cudaGetSymbolAddress(&deg_ptr, g_deg);

    cudaMemsetAsync(deg_ptr, 0, NN * sizeof(int));
    k_deg<<<(E + 255) / 256, 256>>>(dst, E);
    k_dinv<<<(NN + 255) / 256, 256>>>();

    k_gemm1<<<(NN + TR - 1) / TR, 128>>>(x, W0);

    k_edge1<<<(4 * E + 255) / 256, 256>>>(src, dst, E);

    k_mid<<<(NN / 4 + 255) / 256, 256>>>(W1);

    k_edge2<<<(2 * E + 255) / 256, 256>>>(src, dst, E);

    k_final<<<(NN * NL + 255) / 256, 256>>>(out);
}

// round 13
// speedup vs baseline: 1.4757x; 1.1713x over previous
#include <cuda_runtime.h>
#include <cuda_fp16.h>

#define NN 100000
#define F_IN 256
#define CH 16
#define CH2 8
#define NL 7

// ---------------- scratch (static device memory; no allocs) ----------------
__device__ __align__(128) __half g_hs  [NN * CH];   // layer1 transform (fp16, pre-scaled)
__device__ __align__(128) __half g_out1[NN * CH];   // layer1 accumulator (fp16)
__device__ __align__(128) __half g_hs2 [NN * CH2];  // layer2 transform (fp16, padded)
__device__ __align__(128) __half g_out2[NN * CH2];  // layer2 accumulator (fp16, padded)
__device__ float g_dinv[NN];
__device__ int   g_deg [NN];

// vector f16x2 reduction (no return): 8 halves / 16B per op (sm_90+)
__device__ __forceinline__ void red_add_f16x8(__half* p, uint4 v) {
    asm volatile("red.global.add.noftz.v4.f16x2 [%0], {%1, %2, %3, %4};"
                 :: "l"(p), "r"(v.x), "r"(v.y), "r"(v.z), "r"(v.w) : "memory");
}

// packed dual fp32 FMA (sm_100a+)
__device__ __forceinline__ void ffma2(unsigned long long& d,
                                      unsigned long long a,
                                      unsigned long long b) {
    asm("fma.rn.f32x2 %0, %1, %2, %0;" : "+l"(d) : "l"(a), "l"(b));
}
__device__ __forceinline__ float f32x2_sum(unsigned long long v) {
    float lo = __uint_as_float((unsigned int)(v & 0xffffffffull));
    float hi = __uint_as_float((unsigned int)(v >> 32));
    return lo + hi;
}
__device__ __forceinline__ unsigned int h2raw(__half2 h) {
    return *reinterpret_cast<unsigned int*>(&h);
}

// ---------------- degree / norm ----------------
__global__ void k_deg(const int* __restrict__ dst, int E) {
    int i = blockIdx.x * blockDim.x + threadIdx.x;
    if (i < E) atomicAdd(&g_deg[dst[i]], 1);
}

__global__ void k_dinv() {
    int i = blockIdx.x * blockDim.x + threadIdx.x;
    if (i < NN) g_dinv[i] = rsqrtf((float)(g_deg[i] + 1));   // +1 self loop
}

// ---------------- GEMM1: smem-tiled FFMA2 + cp.async double buffer ----------------
#define TR 96
#define KCH 32
#define NCHUNK (F_IN / KCH)

__device__ __forceinline__ void stage_chunk(const float* __restrict__ x,
                                            int row0, int kc, float* xsbuf, int tid) {
    #pragma unroll
    for (int it = 0; it < 6; it++) {
        int f = tid + 128 * it;
        int r = f >> 3;
        int q = f & 7;
        int grow = row0 + r;
        int ok = (grow < NN);
        const float* gp = x + (size_t)(ok ? grow : 0) * F_IN + kc + 4 * q;
        unsigned saddr = (unsigned)__cvta_generic_to_shared(xsbuf + r * 36 + 4 * q);
        int sz = ok ? 16 : 0;
        asm volatile("cp.async.cg.shared.global [%0], [%1], 16, %2;"
                     :: "r"(saddr), "l"(gp), "r"(sz));
    }
}

__global__ void __launch_bounds__(128) k_gemm1(const float* __restrict__ x,
                                               const float* __restrict__ W0) {
    __shared__ float xs[2][TR * 36];   // 2 x 13824 B
    __shared__ float Wp[128 * 32];     // 16384 B
    const int tid = threadIdx.x;
    const int rg  = tid >> 2;
    const int cg  = tid & 3;
    const int row0 = blockIdx.x * TR;

    // stage W0 packed: Wp[(k>>1)*32 + 2*col + (k&1)] = W0[k*16+col]
    #pragma unroll
    for (int i = 0; i < 32; i++) {
        int idx = tid + 128 * i;
        int k   = idx >> 4;
        int col = idx & 15;
        Wp[(k >> 1) * 32 + 2 * col + (k & 1)] = W0[idx];
    }

    stage_chunk(x, row0, 0, xs[0], tid);
    asm volatile("cp.async.commit_group;");

    unsigned long long acc[3][4];
    #pragma unroll
    for (int c = 0; c < 3; c++)
        #pragma unroll
        for (int j = 0; j < 4; j++) acc[c][j] = 0ull;

    for (int ch = 0; ch < NCHUNK; ch++) {
        if (ch + 1 < NCHUNK) {
            stage_chunk(x, row0, (ch + 1) * KCH, xs[(ch + 1) & 1], tid);
            asm volatile("cp.async.commit_group;");
            asm volatile("cp.async.wait_group 1;");
        } else {
            asm volatile("cp.async.wait_group 0;");
        }
        __syncthreads();

        const float* buf = xs[ch & 1];
        const int pbase = ch * (KCH / 2);
        #pragma unroll
        for (int kp = 0; kp < KCH / 2; kp++) {
            const float* wp0 = Wp + (pbase + kp) * 32 + 8 * cg;
            ulonglong2 wA = *(const ulonglong2*)wp0;
            ulonglong2 wB = *(const ulonglong2*)(wp0 + 4);
            #pragma unroll
            for (int c = 0; c < 3; c++) {
                unsigned long long xv =
                    *(const unsigned long long*)(buf + (rg + 32 * c) * 36 + 2 * kp);
                ffma2(acc[c][0], xv, wA.x);
                ffma2(acc[c][1], xv, wA.y);
                ffma2(acc[c][2], xv, wB.x);
                ffma2(acc[c][3], xv, wB.y);
            }
        }
        __syncthreads();
    }

    #pragma unroll
    for (int c = 0; c < 3; c++) {
        int grow = row0 + rg + 32 * c;
        if (grow < NN) {
            float di = g_dinv[grow];
            __half2 a = __floats2half2_rn(f32x2_sum(acc[c][0]) * di,
                                          f32x2_sum(acc[c][1]) * di);
            __half2 b = __floats2half2_rn(f32x2_sum(acc[c][2]) * di,
                                          f32x2_sum(acc[c][3]) * di);
            unsigned long long u = (unsigned long long)h2raw(a)
                                 | ((unsigned long long)h2raw(b) << 32);
            *(unsigned long long*)(g_hs   + (size_t)grow * CH + 4 * cg) = u;
            *(unsigned long long*)(g_out1 + (size_t)grow * CH + 4 * cg) = u; // self loop
        }
    }
}

// ---------------- edge scatter, layer 1 (fp16, 2 lanes/edge) ----------------
__global__ void k_edge1(const int* __restrict__ src, const int* __restrict__ dst, int E) {
    int t = blockIdx.x * blockDim.x + threadIdx.x;
    if (t >= 2 * E) return;
    int e = t >> 1;
    int c = t & 1;   // which 8-half chunk
    int s = src[e];
    int d = dst[e];
    uint4 v = *(const uint4*)(g_hs + (size_t)s * CH + 8 * c);
    red_add_f16x8(g_out1 + (size_t)d * CH + 8 * c, v);
}

// ---------------- mid: h1 = relu(out1*dinv); hs2 = (h1 @ W1)*dinv; init out2 -------
__global__ void __launch_bounds__(256) k_mid(const float* __restrict__ W1) {
    __shared__ float W1s[CH * NL];
    if (threadIdx.x < CH * NL) W1s[threadIdx.x] = W1[threadIdx.x];
    __syncthreads();

    int row = blockIdx.x * blockDim.x + threadIdx.x;
    if (row >= NN) return;

    float di = g_dinv[row];
    float h[CH];
    const __half2* p = (const __half2*)(g_out1 + (size_t)row * CH);
    #pragma unroll
    for (int q = 0; q < 8; q++) {
        float2 f = __half22float2(p[q]);
        h[2 * q + 0] = fmaxf(f.x * di, 0.f);
        h[2 * q + 1] = fmaxf(f.y * di, 0.f);
    }

    float acc[NL];
    #pragma unroll
    for (int j = 0; j < NL; j++) acc[j] = 0.f;
    #pragma unroll
    for (int k = 0; k < CH; k++) {
        float hv = h[k];
        #pragma unroll
        for (int j = 0; j < NL; j++) acc[j] += hv * W1s[k * NL + j];
    }

    __half2 q0 = __floats2half2_rn(acc[0] * di, acc[1] * di);
    __half2 q1 = __floats2half2_rn(acc[2] * di, acc[3] * di);
    __half2 q2 = __floats2half2_rn(acc[4] * di, acc[5] * di);
    __half2 q3 = __floats2half2_rn(acc[6] * di, 0.f);
    uint4 u = make_uint4(h2raw(q0), h2raw(q1), h2raw(q2), h2raw(q3));
    *(uint4*)(g_hs2  + (size_t)row * CH2) = u;
    *(uint4*)(g_out2 + (size_t)row * CH2) = u;   // self loop
}

// ---------------- edge scatter, layer 2 (fp16, 1 lane/edge) ----------------
__global__ void k_edge2(const int* __restrict__ src, const int* __restrict__ dst, int E) {
    int e = blockIdx.x * blockDim.x + threadIdx.x;
    if (e >= E) return;
    int s = src[e];
    int d = dst[e];
    uint4 v = *(const uint4*)(g_hs2 + (size_t)s * CH2);
    red_add_f16x8(g_out2 + (size_t)d * CH2, v);
}

// ---------------- finalize: out = exp(out2*dinv) + 1 ----------------
__global__ void k_final(float* __restrict__ out) {
    int t = blockIdx.x * blockDim.x + threadIdx.x;
    if (t >= NN * NL) return;
    int i = t / NL;
    int j = t - i * NL;
    float v = __half2float(g_out2[(size_t)i * CH2 + j]) * g_dinv[i];
    out[t] = expf(v) + 1.0f;
}

// ---------------- launch ----------------
extern "C" void kernel_launch(void* const* d_in, const int* in_sizes, int n_in,
                              void* d_out, int out_size) {
    const float* x  = (const float*)d_in[0];
    const float* W0 = (const float*)d_in[1];
    const float* W1 = (const float*)d_in[2];
    const int*   ei = (const int*)d_in[3];
    const int E = in_sizes[3] / 2;
    const int* src = ei;
    const int* dst = ei + E;
    float* out = (float*)d_out;

    static void* deg_ptr = nullptr;
    if (!deg_ptr) cudaGetSymbolAddress(&deg_ptr, g_deg);

    cudaMemsetAsync(deg_ptr, 0, NN * sizeof(int));
    k_deg<<<(E + 255) / 256, 256>>>(dst, E);
    k_dinv<<<(NN + 255) / 256, 256>>>();

    k_gemm1<<<(NN + TR - 1) / TR, 128>>>(x, W0);

    k_edge1<<<(2 * E + 255) / 256, 256>>>(src, dst, E);

    k_mid<<<(NN + 255) / 256, 256>>>(W1);

    k_edge2<<<(E + 255) / 256, 256>>>(src, dst, E);

    k_final<<<(NN * NL + 255) / 256, 256>>>(out);
}

// round 16
// speedup vs baseline: 1.5293x; 1.0363x over previous
#include <cuda_runtime.h>
#include <cuda_fp16.h>

#define NN 100000
#define F_IN 256
#define CH 16
#define CH2 8
#define NL 7

// ---------------- scratch (static device memory; no allocs) ----------------
__device__ __align__(128) __half g_hu  [NN * CH];   // layer1 transform, UNSCALED fp16
__device__ __align__(128) __half g_hs  [NN * CH];   // layer1 transform, scaled by dinv[src]
__device__ __align__(128) __half g_out1[NN * CH];   // layer1 accumulator (fp16)
__device__ __align__(128) __half g_hs2 [NN * CH2];  // layer2 transform (fp16, padded)
__device__ __align__(128) __half g_out2[NN * CH2];  // layer2 accumulator (fp16, padded)
__device__ float g_dinv[NN];
__device__ int   g_deg [NN];

// vector f16x2 reduction (no return): 8 halves / 16B per op (sm_90+)
__device__ __forceinline__ void red_add_f16x8(__half* p, uint4 v) {
    asm volatile("red.global.add.noftz.v4.f16x2 [%0], {%1, %2, %3, %4};"
                 :: "l"(p), "r"(v.x), "r"(v.y), "r"(v.z), "r"(v.w) : "memory");
}
__device__ __forceinline__ void red_add_s32(int* p, int v) {
    asm volatile("red.global.add.s32 [%0], %1;" :: "l"(p), "r"(v) : "memory");
}

// packed dual fp32 FMA (sm_100a+)
__device__ __forceinline__ void ffma2(unsigned long long& d,
                                      unsigned long long a,
                                      unsigned long long b) {
    asm("fma.rn.f32x2 %0, %1, %2, %0;" : "+l"(d) : "l"(a), "l"(b));
}
__device__ __forceinline__ float f32x2_sum(unsigned long long v) {
    float lo = __uint_as_float((unsigned int)(v & 0xffffffffull));
    float hi = __uint_as_float((unsigned int)(v >> 32));
    return lo + hi;
}
__device__ __forceinline__ unsigned int h2raw(__half2 h) {
    return *reinterpret_cast<unsigned int*>(&h);
}

// ---------------- degree ----------------
__global__ void k_deg4(const int* __restrict__ dst, int E4, int E) {
    int i = blockIdx.x * blockDim.x + threadIdx.x;
    if (i < E4) {
        int4 d = ((const int4*)dst)[i];
        red_add_s32(&g_deg[d.x], 1);
        red_add_s32(&g_deg[d.y], 1);
        red_add_s32(&g_deg[d.z], 1);
        red_add_s32(&g_deg[d.w], 1);
    }
    // tail
    int t = 4 * E4 + i;
    if (i < E - 4 * E4) red_add_s32(&g_deg[dst[t]], 1);
}

// ---------------- GEMM1: unscaled h (NO deg dependency) ----------------
#define TR 96
#define KCH 32
#define NCHUNK (F_IN / KCH)

__device__ __forceinline__ void stage_chunk(const float* __restrict__ x,
                                            int row0, int kc, float* xsbuf, int tid) {
    #pragma unroll
    for (int it = 0; it < 6; it++) {
        int f = tid + 128 * it;
        int r = f >> 3;
        int q = f & 7;
        int grow = row0 + r;
        int ok = (grow < NN);
        const float* gp = x + (size_t)(ok ? grow : 0) * F_IN + kc + 4 * q;
        unsigned saddr = (unsigned)__cvta_generic_to_shared(xsbuf + r * 36 + 4 * q);
        int sz = ok ? 16 : 0;
        asm volatile("cp.async.cg.shared.global [%0], [%1], 16, %2;"
                     :: "r"(saddr), "l"(gp), "r"(sz));
    }
}

__global__ void __launch_bounds__(128) k_gemm1(const float* __restrict__ x,
                                               const float* __restrict__ W0) {
    __shared__ float xs[2][TR * 36];   // 2 x 13824 B
    __shared__ float Wp[128 * 32];     // 16384 B
    const int tid = threadIdx.x;
    const int rg  = tid >> 2;
    const int cg  = tid & 3;
    const int row0 = blockIdx.x * TR;

    // stage W0 packed: Wp[(k>>1)*32 + 2*col + (k&1)] = W0[k*16+col]
    #pragma unroll
    for (int i = 0; i < 32; i++) {
        int idx = tid + 128 * i;
        int k   = idx >> 4;
        int col = idx & 15;
        Wp[(k >> 1) * 32 + 2 * col + (k & 1)] = W0[idx];
    }

    stage_chunk(x, row0, 0, xs[0], tid);
    asm volatile("cp.async.commit_group;");

    unsigned long long acc[3][4];
    #pragma unroll
    for (int c = 0; c < 3; c++)
        #pragma unroll
        for (int j = 0; j < 4; j++) acc[c][j] = 0ull;

    for (int ch = 0; ch < NCHUNK; ch++) {
        if (ch + 1 < NCHUNK) {
            stage_chunk(x, row0, (ch + 1) * KCH, xs[(ch + 1) & 1], tid);
            asm volatile("cp.async.commit_group;");
            asm volatile("cp.async.wait_group 1;");
        } else {
            asm volatile("cp.async.wait_group 0;");
        }
        __syncthreads();

        const float* buf = xs[ch & 1];
        const int pbase = ch * (KCH / 2);
        #pragma unroll
        for (int kp = 0; kp < KCH / 2; kp++) {
            const float* wp0 = Wp + (pbase + kp) * 32 + 8 * cg;
            ulonglong2 wA = *(const ulonglong2*)wp0;
            ulonglong2 wB = *(const ulonglong2*)(wp0 + 4);
            #pragma unroll
            for (int c = 0; c < 3; c++) {
                unsigned long long xv =
                    *(const unsigned long long*)(buf + (rg + 32 * c) * 36 + 2 * kp);
                ffma2(acc[c][0], xv, wA.x);
                ffma2(acc[c][1], xv, wA.y);
                ffma2(acc[c][2], xv, wB.x);
                ffma2(acc[c][3], xv, wB.y);
            }
        }
        __syncthreads();
    }

    #pragma unroll
    for (int c = 0; c < 3; c++) {
        int grow = row0 + rg + 32 * c;
        if (grow < NN) {
            __half2 a = __floats2half2_rn(f32x2_sum(acc[c][0]), f32x2_sum(acc[c][1]));
            __half2 b = __floats2half2_rn(f32x2_sum(acc[c][2]), f32x2_sum(acc[c][3]));
            unsigned long long u = (unsigned long long)h2raw(a)
                                 | ((unsigned long long)h2raw(b) << 32);
            *(unsigned long long*)(g_hu + (size_t)grow * CH + 4 * cg) = u;
        }
    }
}

// ---------------- join: dinv = rsqrt(deg+1); hs = hu*dinv; out1 = hs ----------------
__global__ void __launch_bounds__(256) k_scale() {
    int i = blockIdx.x * blockDim.x + threadIdx.x;
    if (i >= NN) return;
    float di = rsqrtf((float)(g_deg[i] + 1));
    g_dinv[i] = di;
    const __half2* p = (const __half2*)(g_hu + (size_t)i * CH);
    unsigned int r[8];
    #pragma unroll
    for (int q = 0; q < 8; q++) {
        float2 f = __half22float2(p[q]);
        r[q] = h2raw(__floats2half2_rn(f.x * di, f.y * di));
    }
    uint4* hs  = (uint4*)(g_hs   + (size_t)i * CH);
    uint4* o1  = (uint4*)(g_out1 + (size_t)i * CH);
    uint4 lo = make_uint4(r[0], r[1], r[2], r[3]);
    uint4 hi = make_uint4(r[4], r[5], r[6], r[7]);
    hs[0] = lo; hs[1] = hi;
    o1[0] = lo; o1[1] = hi;   // self-loop init
}

// ---------------- edge scatter, layer 1 (fp16, 2 lanes/edge) ----------------
__global__ void k_edge1(const int* __restrict__ src, const int* __restrict__ dst, int E) {
    int t = blockIdx.x * blockDim.x + threadIdx.x;
    if (t >= 2 * E) return;
    int e = t >> 1;
    int c = t & 1;
    int s = src[e];
    int d = dst[e];
    uint4 v = *(const uint4*)(g_hs + (size_t)s * CH + 8 * c);
    red_add_f16x8(g_out1 + (size_t)d * CH + 8 * c, v);
}

// ---------------- mid: h1 = relu(out1*dinv); hs2 = (h1 @ W1)*dinv; init out2 -------
__global__ void __launch_bounds__(256) k_mid(const float* __restrict__ W1) {
    __shared__ float W1s[CH * NL];
    if (threadIdx.x < CH * NL) W1s[threadIdx.x] = W1[threadIdx.x];
    __syncthreads();

    int row = blockIdx.x * blockDim.x + threadIdx.x;
    if (row >= NN) return;

    float di = g_dinv[row];
    float h[CH];
    const __half2* p = (const __half2*)(g_out1 + (size_t)row * CH);
    #pragma unroll
    for (int q = 0; q < 8; q++) {
        float2 f = __half22float2(p[q]);
        h[2 * q + 0] = fmaxf(f.x * di, 0.f);
        h[2 * q + 1] = fmaxf(f.y * di, 0.f);
    }

    float acc[NL];
    #pragma unroll
    for (int j = 0; j < NL; j++) acc[j] = 0.f;
    #pragma unroll
    for (int k = 0; k < CH; k++) {
        float hv = h[k];
        #pragma unroll
        for (int j = 0; j < NL; j++) acc[j] += hv * W1s[k * NL + j];
    }

    __half2 q0 = __floats2half2_rn(acc[0] * di, acc[1] * di);
    __half2 q1 = __floats2half2_rn(acc[2] * di, acc[3] * di);
    __half2 q2 = __floats2half2_rn(acc[4] * di, acc[5] * di);
    __half2 q3 = __floats2half2_rn(acc[6] * di, 0.f);
    uint4 u = make_uint4(h2raw(q0), h2raw(q1), h2raw(q2), h2raw(q3));
    *(uint4*)(g_hs2  + (size_t)row * CH2) = u;
    *(uint4*)(g_out2 + (size_t)row * CH2) = u;   // self loop
}

// ---------------- edge scatter, layer 2 (fp16, 1 lane/edge) ----------------
__global__ void k_edge2(const int* __restrict__ src, const int* __restrict__ dst, int E) {
    int e = blockIdx.x * blockDim.x + threadIdx.x;
    if (e >= E) return;
    int s = src[e];
    int d = dst[e];
    uint4 v = *(const uint4*)(g_hs2 + (size_t)s * CH2);
    red_add_f16x8(g_out2 + (size_t)d * CH2, v);
}

// ---------------- finalize: out = exp(out2*dinv) + 1 ----------------
__global__ void k_final(float* __restrict__ out) {
    int t = blockIdx.x * blockDim.x + threadIdx.x;
    if (t >= NN * NL) return;
    int i = t / NL;
    int j = t - i * NL;
    float v = __half2float(g_out2[(size_t)i * CH2 + j]) * g_dinv[i];
    out[t] = expf(v) + 1.0f;
}

// ---------------- launch ----------------
extern "C" void kernel_launch(void* const* d_in, const int* in_sizes, int n_in,
                              void* d_out, int out_size) {
    const float* x  = (const float*)d_in[0];
    const float* W0 = (const float*)d_in[1];
    const float* W1 = (const float*)d_in[2];
    const int*   ei = (const int*)d_in[3];
    const int E = in_sizes[3] / 2;
    const int* src = ei;
    const int* dst = ei + E;
    float* out = (float*)d_out;

    static void* deg_ptr = nullptr;
    static cudaStream_t s1 = nullptr;
    static cudaEvent_t ev_fork = nullptr, ev_join = nullptr;
    if (!deg_ptr) {
        cudaGetSymbolAddress(&deg_ptr, g_deg);
        cudaStreamCreateWithFlags(&s1, cudaStreamNonBlocking);
        cudaEventCreateWithFlags(&ev_fork, cudaEventDisableTiming);
        cudaEventCreateWithFlags(&ev_join, cudaEventDisableTiming);
    }

    // fork: degree chain on s1, GEMM (independent of degrees) on main stream
    cudaEventRecord(ev_fork, 0);
    cudaStreamWaitEvent(s1, ev_fork, 0);

    cudaMemsetAsync(deg_ptr, 0, NN * sizeof(int), s1);
    int E4 = E / 4;
    k_deg4<<<(max(E4, E - 4 * E4) + 255) / 256, 256, 0, s1>>>(dst, E4, E);

    k_gemm1<<<(NN + TR - 1) / TR, 128>>>(x, W0);

    // join
    cudaEventRecord(ev_join, s1);
    cudaStreamWaitEvent(0, ev_join, 0);

    k_scale<<<(NN + 255) / 256, 256>>>();

    k_edge1<<<(2 * E + 255) / 256, 256>>>(src, dst, E);

    k_mid<<<(NN + 255) / 256, 256>>>(W1);

    k_edge2<<<(E + 255) / 256, 256>>>(src, dst, E);

    k_final<<<(NN * NL + 255) / 256, 256>>>(out);
}